// round 17
// baseline (speedup 1.0000x reference)
#include <cuda_runtime.h>
#include <cuda_fp16.h>
#include <stdint.h>
#include <float.h>

#define NROWS   65536
#define DIMS    256
#define NCODES  1024
#define TM      64         // rows per block
#define TC      32         // codes per chunk
#define NCHUNK  (NCODES / TC)
#define MARGIN  2e-3f      // R12-R16-proven for f16-acc pipeline
#define ASTRB   528        // f16 row stride bytes -> conflict-free ldmatrix

// ---- smem layout (bytes) -------------------------------------------------
#define OFF_A      0                         // 64 x 528                  33792
#define OFF_B      33792                     // 32 x 528                  16896
// aliased into B region (only used AFTER the chunk loop):
#define OFF_FMIN   33792                     // i32[64]                     256
#define OFF_BEST   34048                     // u64[64]                     512
#define OFF_IDX    34560                     // i32[64]                     256
#define OFF_ROVF   34816                     // i32[64]                     256
#define OFF_OVFL   35072                     // i32 count + i32[64]         260
#define OFF_RED    35336                     // double[256]                2048
// persistent:
#define OFF_CMB    50688                     // u32[4*32*8] k-half combine 4096
#define OFF_Z2     54784                     // f32[64]                     256
#define SMEM_BYTES 55040

__device__ float          g_e2[NCODES];
__device__ unsigned short g_ehf[NCODES * DIMS];   // f16 codebook (pre-converted)
__device__ double         g_loss_accum;

// ---------------------------------------------------------------------------
__device__ __forceinline__ uint32_t smem_u32(const void* p) {
    uint32_t a;
    asm("{ .reg .u64 t; cvta.to.shared.u64 t, %1; cvt.u32.u64 %0, t; }"
        : "=r"(a) : "l"(p));
    return a;
}
__device__ __forceinline__ void ldm_x4(uint32_t* r, uint32_t a) {
    asm volatile("ldmatrix.sync.aligned.m8n8.x4.shared.b16 {%0,%1,%2,%3}, [%4];"
                 : "=r"(r[0]), "=r"(r[1]), "=r"(r[2]), "=r"(r[3]) : "r"(a));
}
// f16 x f16 -> f16 accumulators (2 packed regs)
__device__ __forceinline__ void mma_f16(uint32_t* c, const uint32_t* a,
                                        const uint32_t* b) {
    asm volatile(
        "mma.sync.aligned.m16n8k16.row.col.f16.f16.f16.f16 "
        "{%0,%1},{%2,%3,%4,%5},{%6,%7},{%0,%1};"
        : "+r"(c[0]), "+r"(c[1])
        : "r"(a[0]), "r"(a[1]), "r"(a[2]), "r"(a[3]), "r"(b[0]), "r"(b[1]));
}

// ---------------------------------------------------------------------------
// prep: per-code e2 + f16 codebook + loss zeroing (one warp per code)
// ---------------------------------------------------------------------------
__global__ void vq_prep(const float* __restrict__ emb) {
    if (blockIdx.x == 0 && threadIdx.x == 0) g_loss_accum = 0.0;
    int warp = (blockIdx.x * blockDim.x + threadIdx.x) >> 5;
    int lane = threadIdx.x & 31;
    if (warp < NCODES) {
        const float* row = emb + warp * DIMS;
        float s = 0.f;
#pragma unroll
        for (int i = 0; i < DIMS / 32; i++) {
            float v = row[lane + 32 * i];
            s = __fadd_rn(s, __fmul_rn(v, v));
        }
#pragma unroll
        for (int o = 16; o > 0; o >>= 1)
            s = __fadd_rn(s, __shfl_down_sync(0xffffffffu, s, o));
        if (lane == 0) g_e2[warp] = s;
        unsigned short q[8];
#pragma unroll
        for (int j = 0; j < 8; j++) {
            __half h = __float2half_rn(row[lane * 8 + j]);
            q[j] = *(unsigned short*)&h;
        }
        *(uint4*)(g_ehf + (size_t)warp * DIMS + lane * 8) = *(uint4*)q;
    }
}

// canonical exact fp32 distance (R1-proven formula/rounding) + tiebreak pack
__device__ __forceinline__ unsigned long long exact_dist(
    const float* __restrict__ zrow, const float* __restrict__ emb,
    int code, float z2) {
    const float4* zr = (const float4*)zrow;
    const float4* er = (const float4*)(emb + (size_t)code * DIMS);
    float d0 = 0.f, d1 = 0.f, d2 = 0.f, d3 = 0.f;
#pragma unroll 8
    for (int k4 = 0; k4 < DIMS / 4; k4++) {
        float4 zv = __ldg(&zr[k4]);
        float4 ev = __ldg(&er[k4]);
        d0 = fmaf(zv.x, ev.x, d0);
        d1 = fmaf(zv.y, ev.y, d1);
        d2 = fmaf(zv.z, ev.z, d2);
        d3 = fmaf(zv.w, ev.w, d3);
    }
    float dot  = __fadd_rn(__fadd_rn(d0, d1), __fadd_rn(d2, d3));
    float t    = __fadd_rn(z2, __ldg(&g_e2[code]));
    float dist = __fsub_rn(t, __fmul_rn(2.0f, dot));
    return ((unsigned long long)__float_as_uint(dist) << 32) | (unsigned)code;
}

// ---------------------------------------------------------------------------
__global__ void __launch_bounds__(256, 4)
vq_main(const float* __restrict__ z, const float* __restrict__ emb,
        float* __restrict__ out) {
    extern __shared__ char sm[];
    float*  z2sm  = (float*)(sm + OFF_Z2);
    uint32_t* cmb = (uint32_t*)(sm + OFF_CMB);
    int*    fminI = (int*)(sm + OFF_FMIN);
    unsigned long long* bestU = (unsigned long long*)(sm + OFF_BEST);
    int*    idxs  = (int*)(sm + OFF_IDX);
    int*    rowOvf= (int*)(sm + OFF_ROVF);
    int*    ovfl  = (int*)(sm + OFF_OVFL);
    double* red   = (double*)(sm + OFF_RED);

    const int tid  = threadIdx.x;
    const int lane = tid & 31;
    const int warp = tid >> 5;
    const int kh   = warp & 1;           // k-half: 0 -> k 0..127, 1 -> 128..255
    const int wc   = (warp >> 1) & 1;    // code group: wc*16 .. +15
    const int wr   = warp >> 2;          // row group: wr*32 .. +31
    const int g    = lane >> 2;          // 0..7
    const int colb = (lane & 3) * 2;
    const int rowBase = blockIdx.x * TM;
    const float* zblk = z + (size_t)rowBase * DIMS;
    const uint32_t smb = smem_u32(sm);

    // ---- stage A (z tile, fp32->f16 once, padded row-major) ----
#pragma unroll 4
    for (int i = tid; i < TM * (DIMS / 4); i += 256) {
        int r  = i >> 6;
        int k4 = i & 63;
        float4 v = __ldg(&((const float4*)zblk)[(size_t)r * (DIMS / 4) + k4]);
        __half2 lo = __float22half2_rn(make_float2(v.x, v.y));
        __half2 hi = __float22half2_rn(make_float2(v.z, v.w));
        uint2 val = make_uint2(*(uint32_t*)&lo, *(uint32_t*)&hi);
        *(uint2*)(sm + OFF_A + (size_t)r * ASTRB + k4 * 8) = val;
    }
    if (tid < TM) {
        const float4* zr = (const float4*)(zblk + (size_t)tid * DIMS);
        float s = 0.f;
        for (int k4 = 0; k4 < DIMS / 4; k4++) {
            float4 v = __ldg(&zr[k4]);
            s = __fadd_rn(s, __fmul_rn(v.x, v.x));
            s = __fadd_rn(s, __fmul_rn(v.y, v.y));
            s = __fadd_rn(s, __fmul_rn(v.z, v.z));
            s = __fadd_rn(s, __fmul_rn(v.w, v.w));
        }
        z2sm[tid] = s;
    }
    // stage B chunk 0 (all threads: 4 x 16B each)
#pragma unroll
    for (int s = 0; s < 4; s++) {
        int cc = (tid >> 5) + s * 8;
        uint4 v = *(const uint4*)(g_ehf + (size_t)cc * DIMS + lane * 8);
        *(uint4*)(sm + OFF_B + (size_t)cc * ASTRB + lane * 16) = v;
    }
    __syncthreads();

    // ---- per-lane ldmatrix base addresses (R6-verified mapping) ----
    const uint32_t aBase0 = smb + OFF_A +
        (uint32_t)((wr * 32 + (lane & 15)) * ASTRB) + (lane >> 4) * 16;
    const uint32_t aBase1 = aBase0 + 16 * ASTRB;
    const int brow = (lane & 7) + ((lane & 16) >> 1);   // 0..15
    const uint32_t bBase = smb + OFF_B +
        (uint32_t)((wc * 16 + brow) * ASTRB) + ((lane >> 3) & 1) * 16;
    const uint32_t kOff = (uint32_t)kh * 8 * 32;        // k-half byte offset

    float z2sl[4];
#pragma unroll
    for (int s = 0; s < 4; s++) z2sl[s] = z2sm[wr * 32 + s * 8 + g];

    // per-slot top-3 tracking (kh==0 threads only produce candidates)
    float b1[4], b2[4], b3[4];
    int   c1[4], c2[4];
#pragma unroll
    for (int s = 0; s < 4; s++) {
        b1[s] = FLT_MAX; b2[s] = FLT_MAX; b3[s] = FLT_MAX;
        c1[s] = 0; c2[s] = 0;
    }

    const int cmbIdx = ((warp >> 1) * 32 + lane) * 8;

    // ===== chunk loop: k-split f16 HMMA, combine, overlapped staging =======
    for (int c = 0; c < NCHUNK; c++) {
        uint32_t acc[8];                  // [m*4 + n*2 + h] f16x2
#pragma unroll
        for (int j = 0; j < 8; j++) acc[j] = 0u;

#pragma unroll
        for (int i = 0; i < 8; i++) {     // this warp's 8 k-steps
            const uint32_t ko = kOff + i * 32;
            uint32_t A0[4], A1[4], B[4];
            ldm_x4(A0, aBase0 + ko);
            ldm_x4(A1, aBase1 + ko);
            ldm_x4(B,  bBase  + ko);
            mma_f16(&acc[0], A0, &B[0]);  // m0 n0
            mma_f16(&acc[2], A0, &B[2]);  // m0 n1
            mma_f16(&acc[4], A1, &B[0]);  // m1 n0
            mma_f16(&acc[6], A1, &B[2]);  // m1 n1
        }

        // publish kh=1 partial accumulators
        if (kh) {
#pragma unroll
            for (int j = 0; j < 8; j++) cmb[cmbIdx + j] = acc[j];
        }
        __syncthreads();                  // acc published; B readers done

        if (!kh) {
            // combine halves + distances + top-3 tracking
            const int cBase = c * TC + wc * 16 + colb;
#pragma unroll
            for (int m = 0; m < 2; m++)
#pragma unroll
                for (int h = 0; h < 2; h++) {
                    const int slot = m * 2 + h;
                    const float z2e = z2sl[slot];
                    float kv[4];
                    float smin = FLT_MAX;
#pragma unroll
                    for (int n = 0; n < 2; n++) {
                        int j = m * 4 + n * 2 + h;
                        float2 f0 = __half22float2(*(const __half2*)&acc[j]);
                        float2 f1 = __half22float2(
                            *(const __half2*)&cmb[cmbIdx + j]);
                        int code = cBase + n * 8;
                        float e20 = __ldg(&g_e2[code]);
                        float e21 = __ldg(&g_e2[code + 1]);
                        float da0 = fmaf(-2.f, f0.x + f1.x, z2e + e20);
                        float da1 = fmaf(-2.f, f0.y + f1.y, z2e + e21);
                        kv[n * 2]     = da0;
                        kv[n * 2 + 1] = da1;
                        smin = fminf(smin, fminf(da0, da1));
                    }
                    if (smin < b3[slot]) {
#pragma unroll
                        for (int q = 0; q < 4; q++) {
                            float v = kv[q];
                            int   code = cBase + (q >> 1) * 8 + (q & 1);
                            if (v < b1[slot]) {
                                b3[slot] = b2[slot];
                                b2[slot] = b1[slot]; c2[slot] = c1[slot];
                                b1[slot] = v;        c1[slot] = code;
                            } else if (v < b2[slot]) {
                                b3[slot] = b2[slot];
                                b2[slot] = v;        c2[slot] = code;
                            } else if (v < b3[slot]) {
                                b3[slot] = v;
                            }
                        }
                    }
                }
        } else if (c + 1 < NCHUNK) {
            // kh=1 warps stage next B chunk (overlaps kh=0 tail)
            const int wid1 = warp >> 1;   // 0..3
#pragma unroll
            for (int s = 0; s < 8; s++) {
                int cc = wid1 + s * 4;
                uint4 v = *(const uint4*)(g_ehf +
                          (size_t)((c + 1) * TC + cc) * DIMS + lane * 8);
                *(uint4*)(sm + OFF_B + (size_t)cc * ASTRB + lane * 16) = v;
            }
        }
        __syncthreads();                  // B ready / tail done
    }

    // ---- init aliased post-loop state ----
    if (tid < TM) {
        fminI[tid]  = 0x7f800000;
        bestU[tid]  = ~0ull;
        rowOvf[tid] = 0;
    }
    if (tid == 0) ovfl[0] = 0;
    __syncthreads();

#pragma unroll
    for (int s = 0; s < 4; s++)
        atomicMin(&fminI[wr * 32 + s * 8 + g], __float_as_int(b1[s]));
    __syncthreads();

    // ---- rescore top-2 candidates; flag rows needing full scan ----
    // (kh==1 threads have b1..b3 == FLT_MAX: naturally no-ops)
#pragma unroll
    for (int s = 0; s < 4; s++) {
        const int row = wr * 32 + s * 8 + g;
        const float thr = __int_as_float(fminI[row]) + MARGIN;
        if (b1[s] <= thr)
            atomicMin(&bestU[row],
                      exact_dist(zblk + (size_t)row * DIMS, emb, c1[s],
                                 z2sm[row]));
        if (b2[s] <= thr)
            atomicMin(&bestU[row],
                      exact_dist(zblk + (size_t)row * DIMS, emb, c2[s],
                                 z2sm[row]));
        if (b3[s] <= thr) rowOvf[row] = 1;
    }
    __syncthreads();

    // ---- overflow rows: full exact scan (safety net, ~never taken) ----
    if (tid < TM && rowOvf[tid]) {
        int p = atomicAdd(&ovfl[0], 1);
        ovfl[1 + p] = tid;
    }
    __syncthreads();
    int novf = ovfl[0];
    for (int f = 0; f < novf; f++) {
        int row = ovfl[1 + f];
        float z2r = z2sm[row];
        for (int code = tid; code < NCODES; code += 256) {
            unsigned long long p =
                exact_dist(zblk + (size_t)row * DIMS, emb, code, z2r);
            atomicMin(&bestU[row], p);
        }
    }
    if (novf) __syncthreads();

    if (tid < TM) idxs[tid] = (int)(bestU[tid] & 0xffffffffull);
    __syncthreads();

    // ================= epilogue: gather / STE / loss ======================
    double lsum = 0.0;
    float* outblk = out + (size_t)rowBase * DIMS;
#pragma unroll 4
    for (int i = tid; i < TM * (DIMS / 4); i += 256) {
        int r  = i >> 6;
        int k4 = i & 63;
        float4 zv = __ldg(&((const float4*)zblk)[(size_t)r * (DIMS / 4) + k4]);
        float4 qv = __ldg(&((const float4*)(emb + (size_t)idxs[r] * DIMS))[k4]);
        float4 ov; float d;
        d = __fsub_rn(qv.x, zv.x); ov.x = __fadd_rn(zv.x, d); lsum += (double)__fmul_rn(d, d);
        d = __fsub_rn(qv.y, zv.y); ov.y = __fadd_rn(zv.y, d); lsum += (double)__fmul_rn(d, d);
        d = __fsub_rn(qv.z, zv.z); ov.z = __fadd_rn(zv.z, d); lsum += (double)__fmul_rn(d, d);
        d = __fsub_rn(qv.w, zv.w); ov.w = __fadd_rn(zv.w, d); lsum += (double)__fmul_rn(d, d);
        ((float4*)outblk)[i] = ov;
    }
    red[tid] = lsum;
    __syncthreads();
    for (int s = 128; s > 0; s >>= 1) {
        if (tid < s) red[tid] += red[tid + s];
        __syncthreads();
    }
    if (tid == 0) atomicAdd(&g_loss_accum, red[0]);
}

// ---------------------------------------------------------------------------
__global__ void vq_finalize(float* __restrict__ out, int out_size) {
    double mean = g_loss_accum / (double)((size_t)NROWS * DIMS);
    float loss = (float)(0.5 * mean);
    out[out_size - 2] = loss;   // commitment_loss
    out[out_size - 1] = loss;   // emb_loss
}

// ---------------------------------------------------------------------------
extern "C" void kernel_launch(void* const* d_in, const int* in_sizes, int n_in,
                              void* d_out, int out_size) {
    const float* z   = (const float*)d_in[0];
    const float* emb = (const float*)d_in[1];
    if (n_in >= 2 && in_sizes[0] == NCODES * DIMS && in_sizes[1] == NROWS * DIMS) {
        emb = (const float*)d_in[0];
        z   = (const float*)d_in[1];
    }
    float* out = (float*)d_out;

    vq_prep<<<(NCODES * 32 + 255) / 256, 256>>>(emb);

    cudaFuncSetAttribute(vq_main, cudaFuncAttributeMaxDynamicSharedMemorySize,
                         SMEM_BYTES);
    vq_main<<<NROWS / TM, 256, SMEM_BYTES>>>(z, emb, out);

    vq_finalize<<<1, 1>>>(out, out_size);
}